// round 3
// baseline (speedup 1.0000x reference)
#include <cuda_runtime.h>

#define DIMK   512
#define NCLS   11003
#define NBATCH 256
#define NPART  5
#define NSEGC  6
#define NPIX   4096
#define SCALE_C 28.0f

// ---------------- device scratch (no allocations allowed) ----------------
__device__ float g_invW[11008];
__device__ float g_invRow[3072];          // [0,512) v|t, [512,1792) part, [1792,3072) attr
__device__ float g_rowSumExp[512];
__device__ float g_labelLogit[512];
__device__ float g_sim[NPART * 256 * 256];
__device__ int   g_rowTop[NPART * 256 * 8];
__device__ int   g_colTop[NPART * 256 * 8];
__device__ unsigned char g_boost1[NPART * 256];
__device__ unsigned char g_boost2[NPART * 256];
__device__ float g_accum[4];              // 0: mask ce, 1: global, 2: local

// ---------------- helpers ----------------
__device__ __forceinline__ float softplusf(float x) {
    return x > 15.f ? x : log1pf(__expf(x));
}

__device__ __forceinline__ unsigned long long pk2(float lo, float hi) {
    unsigned long long r;
    asm("mov.b64 %0, {%1, %2};" : "=l"(r) : "f"(lo), "f"(hi));
    return r;
}
__device__ __forceinline__ void upk2(unsigned long long v, float& lo, float& hi) {
    asm("mov.b64 {%0, %1}, %2;" : "=f"(lo), "=f"(hi) : "l"(v));
}
__device__ __forceinline__ unsigned long long ffma2(unsigned long long a,
                                                    unsigned long long b,
                                                    unsigned long long c) {
    unsigned long long d;
    asm("fma.rn.f32x2 %0, %1, %2, %3;" : "=l"(d) : "l"(a), "l"(b), "l"(c));
    return d;
}

// block (256 or 512 threads) sum reduce; result valid on thread 0
__device__ __forceinline__ float blockReduceSum(float v, float* sh) {
    int t = threadIdx.x;
    #pragma unroll
    for (int o = 16; o; o >>= 1) v += __shfl_xor_sync(0xffffffffu, v, o);
    if ((t & 31) == 0) sh[t >> 5] = v;
    __syncthreads();
    int nw = (blockDim.x + 31) >> 5;
    if (t < 32) {
        v = (t < nw) ? sh[t] : 0.f;
        #pragma unroll
        for (int o = 16; o; o >>= 1) v += __shfl_xor_sync(0xffffffffu, v, o);
    }
    return v;
}

// ---------------- init ----------------
__global__ void k_init() {
    int t = blockIdx.x * blockDim.x + threadIdx.x;
    if (t < 512) { g_rowSumExp[t] = 0.f; g_labelLogit[t] = 0.f; }
    if (t < NPART * 256) { g_boost1[t] = 0; g_boost2[t] = 0; }
    if (t < 4) g_accum[t] = 0.f;
}

// ---------------- W column inverse norms ----------------
__global__ void k_colnorm(const float* __restrict__ W) {
    int c = blockIdx.x * blockDim.x + threadIdx.x;
    if (c >= NCLS) return;
    float s = 0.f;
    #pragma unroll 8
    for (int d = 0; d < DIMK; d++) {
        float w = W[d * NCLS + c];
        s = fmaf(w, w, s);
    }
    g_invW[c] = rsqrtf(s);
}

// ---------------- row inverse norms (v,t,part,attr) ----------------
__global__ void k_rownorm(const float* __restrict__ vis, const float* __restrict__ txt,
                          const float* __restrict__ pe, const float* __restrict__ ae) {
    int warp = (blockIdx.x * blockDim.x + threadIdx.x) >> 5;
    int lane = threadIdx.x & 31;
    if (warp >= 3072) return;
    const float* src;
    if (warp < 256)       src = vis + warp * DIMK;
    else if (warp < 512)  src = txt + (warp - 256) * DIMK;
    else if (warp < 1792) src = pe + (warp - 512) * DIMK;
    else                  src = ae + (warp - 1792) * DIMK;
    float s = 0.f;
    #pragma unroll 4
    for (int j = lane; j < DIMK; j += 32) { float v = src[j]; s = fmaf(v, v, s); }
    #pragma unroll
    for (int o = 16; o; o >>= 1) s += __shfl_xor_sync(0xffffffffu, s, o);
    if (!lane) g_invRow[warp] = rsqrtf(s);
}

// ---------------- instance loss: fused GEMM (512 x 11003 x 512) + online sumexp ----------------
__global__ __launch_bounds__(256) void k_instance(
    const float* __restrict__ vis, const float* __restrict__ txt,
    const float* __restrict__ W, const int* __restrict__ labels) {
    __shared__ float As[16][132];
    __shared__ float Bs[16][128];
    int tid = threadIdx.x;
    int tx = tid & 15, ty = tid >> 4;
    int row0 = blockIdx.y * 128;
    int col0 = blockIdx.x * 128;

    unsigned long long acc[8][4];
    #pragma unroll
    for (int i = 0; i < 8; i++)
        #pragma unroll
        for (int j = 0; j < 4; j++) acc[i][j] = 0ull;

    int am = tid >> 1, ah = tid & 1;          // A loader: row am, k-half ah
    int arow = row0 + am;
    const float* aptr = (arow < 256) ? (vis + arow * DIMK) : (txt + (arow - 256) * DIMK);
    int bk = tid >> 4;                         // B loader: k row
    int bc = (tid & 15) * 8;                   // 8 consecutive cols

    for (int kt = 0; kt < DIMK; kt += 16) {
        float4 a0 = *(const float4*)(aptr + kt + ah * 8);
        float4 a1 = *(const float4*)(aptr + kt + ah * 8 + 4);
        As[ah * 8 + 0][am] = a0.x; As[ah * 8 + 1][am] = a0.y;
        As[ah * 8 + 2][am] = a0.z; As[ah * 8 + 3][am] = a0.w;
        As[ah * 8 + 4][am] = a1.x; As[ah * 8 + 5][am] = a1.y;
        As[ah * 8 + 6][am] = a1.z; As[ah * 8 + 7][am] = a1.w;
        #pragma unroll
        for (int j = 0; j < 8; j++) {
            int c = col0 + bc + j;
            Bs[bk][bc + j] = (c < NCLS) ? W[(kt + bk) * NCLS + c] : 0.f;
        }
        __syncthreads();
        #pragma unroll
        for (int k = 0; k < 16; k++) {
            float4 af0 = *(const float4*)&As[k][ty * 8];
            float4 af1 = *(const float4*)&As[k][ty * 8 + 4];
            const unsigned long long* bp = (const unsigned long long*)&Bs[k][tx * 8];
            unsigned long long b0 = bp[0], b1 = bp[1], b2 = bp[2], b3 = bp[3];
            float a[8] = {af0.x, af0.y, af0.z, af0.w, af1.x, af1.y, af1.z, af1.w};
            #pragma unroll
            for (int ri = 0; ri < 8; ri++) {
                unsigned long long aa = pk2(a[ri], a[ri]);
                acc[ri][0] = ffma2(aa, b0, acc[ri][0]);
                acc[ri][1] = ffma2(aa, b1, acc[ri][1]);
                acc[ri][2] = ffma2(aa, b2, acc[ri][2]);
                acc[ri][3] = ffma2(aa, b3, acc[ri][3]);
            }
        }
        __syncthreads();
    }

    int rbase = row0 + ty * 8;
    int cbase = col0 + tx * 8;
    #pragma unroll
    for (int ri = 0; ri < 8; ri++) {
        int row = rbase + ri;
        float invA = g_invRow[row];
        int lbl = labels[row];
        float rs = 0.f;
        #pragma unroll
        for (int cj = 0; cj < 4; cj++) {
            float d0, d1;
            upk2(acc[ri][cj], d0, d1);
            int c0 = cbase + cj * 2, c1 = c0 + 1;
            if (c0 < NCLS) {
                float lg = SCALE_C * d0 * invA * g_invW[c0];
                rs += __expf(lg - SCALE_C);
                if (c0 == lbl) g_labelLogit[row] = lg;
            }
            if (c1 < NCLS) {
                float lg = SCALE_C * d1 * invA * g_invW[c1];
                rs += __expf(lg - SCALE_C);
                if (c1 == lbl) g_labelLogit[row] = lg;
            }
        }
        #pragma unroll
        for (int o = 1; o < 16; o <<= 1) rs += __shfl_xor_sync(0xffffffffu, rs, o, 16);
        if (tx == 0) atomicAdd(&g_rowSumExp[row], rs);
    }
}

// ---------------- sim GEMMs: z=0 global align (fused), z=1..5 part sims to scratch ----------------
__global__ __launch_bounds__(256) void k_sim(
    const float* __restrict__ vis, const float* __restrict__ txt,
    const float* __restrict__ pe, const float* __restrict__ ae,
    const int* __restrict__ labels) {
    __shared__ float As[32][68];
    __shared__ float Bs[32][68];
    __shared__ float sred[8];
    int z = blockIdx.z;
    int tid = threadIdx.x;
    int tx = tid & 15, ty = tid >> 4;
    int r0 = blockIdx.y * 64, c0 = blockIdx.x * 64;

    const float* abase; const float* bbase; int aIdx, bIdx;
    if (z == 0) { abase = vis; bbase = txt; aIdx = 0; bIdx = 256; }
    else {
        int p = z - 1;
        abase = pe + p * 256 * DIMK; bbase = ae + p * 256 * DIMK;
        aIdx = 512 + p * 256; bIdx = 1792 + p * 256;
    }

    float acc[4][4];
    #pragma unroll
    for (int i = 0; i < 4; i++)
        #pragma unroll
        for (int j = 0; j < 4; j++) acc[i][j] = 0.f;

    int lm = tid >> 2, lseg = tid & 3;
    for (int kt = 0; kt < DIMK; kt += 32) {
        float4 v0 = *(const float4*)(abase + (r0 + lm) * DIMK + kt + lseg * 8);
        float4 v1 = *(const float4*)(abase + (r0 + lm) * DIMK + kt + lseg * 8 + 4);
        As[lseg * 8 + 0][lm] = v0.x; As[lseg * 8 + 1][lm] = v0.y;
        As[lseg * 8 + 2][lm] = v0.z; As[lseg * 8 + 3][lm] = v0.w;
        As[lseg * 8 + 4][lm] = v1.x; As[lseg * 8 + 5][lm] = v1.y;
        As[lseg * 8 + 6][lm] = v1.z; As[lseg * 8 + 7][lm] = v1.w;
        float4 w0 = *(const float4*)(bbase + (c0 + lm) * DIMK + kt + lseg * 8);
        float4 w1 = *(const float4*)(bbase + (c0 + lm) * DIMK + kt + lseg * 8 + 4);
        Bs[lseg * 8 + 0][lm] = w0.x; Bs[lseg * 8 + 1][lm] = w0.y;
        Bs[lseg * 8 + 2][lm] = w0.z; Bs[lseg * 8 + 3][lm] = w0.w;
        Bs[lseg * 8 + 4][lm] = w1.x; Bs[lseg * 8 + 5][lm] = w1.y;
        Bs[lseg * 8 + 6][lm] = w1.z; Bs[lseg * 8 + 7][lm] = w1.w;
        __syncthreads();
        #pragma unroll
        for (int k = 0; k < 32; k++) {
            float4 a = *(const float4*)&As[k][ty * 4];
            float4 b = *(const float4*)&Bs[k][tx * 4];
            acc[0][0] = fmaf(a.x, b.x, acc[0][0]); acc[0][1] = fmaf(a.x, b.y, acc[0][1]);
            acc[0][2] = fmaf(a.x, b.z, acc[0][2]); acc[0][3] = fmaf(a.x, b.w, acc[0][3]);
            acc[1][0] = fmaf(a.y, b.x, acc[1][0]); acc[1][1] = fmaf(a.y, b.y, acc[1][1]);
            acc[1][2] = fmaf(a.y, b.z, acc[1][2]); acc[1][3] = fmaf(a.y, b.w, acc[1][3]);
            acc[2][0] = fmaf(a.z, b.x, acc[2][0]); acc[2][1] = fmaf(a.z, b.y, acc[2][1]);
            acc[2][2] = fmaf(a.z, b.z, acc[2][2]); acc[2][3] = fmaf(a.z, b.w, acc[2][3]);
            acc[3][0] = fmaf(a.w, b.x, acc[3][0]); acc[3][1] = fmaf(a.w, b.y, acc[3][1]);
            acc[3][2] = fmaf(a.w, b.z, acc[3][2]); acc[3][3] = fmaf(a.w, b.w, acc[3][3]);
        }
        __syncthreads();
    }

    if (z == 0) {
        float lsum = 0.f;
        #pragma unroll
        for (int ri = 0; ri < 4; ri++) {
            int r = r0 + ty * 4 + ri;
            int lr = labels[r];
            float ia = g_invRow[aIdx + r];
            #pragma unroll
            for (int ci = 0; ci < 4; ci++) {
                int c = c0 + tx * 4 + ci;
                float s = acc[ri][ci] * ia * g_invRow[bIdx + c];
                lsum += (lr == labels[c]) ? softplusf(6.f - 10.f * s)
                                          : softplusf(40.f * s - 16.f);
            }
        }
        float tot = blockReduceSum(lsum, sred);
        if (threadIdx.x == 0) atomicAdd(&g_accum[1], tot);
    } else {
        int p = z - 1;
        #pragma unroll
        for (int ri = 0; ri < 4; ri++) {
            int r = r0 + ty * 4 + ri;
            float ia = g_invRow[aIdx + r];
            #pragma unroll
            for (int ci = 0; ci < 4; ci++) {
                int c = c0 + tx * 4 + ci;
                g_sim[p * 65536 + r * 256 + c] = acc[ri][ci] * ia * g_invRow[bIdx + c];
            }
        }
    }
}

// ---------------- top-8 per row (mode 0) / per column (mode 1) ----------------
__global__ void k_top8(int mode) {
    int p = blockIdx.y;
    int w = threadIdx.x >> 5, lane = threadIdx.x & 31;
    int r = blockIdx.x * 8 + w;
    const float* base = g_sim + p * 65536;
    float v[8];
    #pragma unroll
    for (int j = 0; j < 8; j++) {
        int e = lane + j * 32;
        v[j] = mode ? base[e * 256 + r] : base[r * 256 + e];
    }
    int* out = (mode ? g_colTop : g_rowTop) + (p * 256 + r) * 8;
    for (int it = 0; it < 8; it++) {
        float bv = v[0]; int bj = 0;
        #pragma unroll
        for (int j = 1; j < 8; j++) if (v[j] > bv) { bv = v[j]; bj = j; }
        float mv = bv; int me = lane + bj * 32;
        #pragma unroll
        for (int o = 16; o; o >>= 1) {
            float ov = __shfl_xor_sync(0xffffffffu, mv, o);
            int oe = __shfl_xor_sync(0xffffffffu, me, o);
            if (ov > mv || (ov == mv && oe < me)) { mv = ov; me = oe; }
        }
        if (lane == 0) out[it] = me;
        if ((me & 31) == lane) v[me >> 5] = -__int_as_float(0x7f800000);
    }
}

// ---------------- boosts (mutual top-k check) ----------------
__global__ void k_boost() {
    int t = threadIdx.x;
    if (t >= 80) return;
    int p = t / 16, rem = t % 16, which = rem >> 3, k = rem & 7;
    if (which == 0) {
        int c = g_rowTop[(p * 256 + p) * 8 + k];
        bool hit = false;
        #pragma unroll
        for (int m = 0; m < 8; m++) hit |= (g_colTop[(p * 256 + c) * 8 + m] == p);
        g_boost1[p * 256 + c] = hit ? 1 : 0;
    } else {
        int r = g_colTop[(p * 256 + p) * 8 + k];
        bool hit = false;
        #pragma unroll
        for (int m = 0; m < 8; m++) hit |= (g_rowTop[(p * 256 + r) * 8 + m] == p);
        g_boost2[p * 256 + r] = hit ? 1 : 0;
    }
}

// ---------------- local align weighted sum (masks arrive as int32: harness has no bool) ----------------
__global__ void k_local(const int* __restrict__ labels,
                        const int* __restrict__ vmask,
                        const int* __restrict__ tmask) {
    __shared__ float sred[8];
    int p = blockIdx.y;
    int r = blockIdx.x;
    int c = threadIdx.x;
    float s = g_sim[p * 65536 + r * 256 + c];
    bool match = labels[r] == labels[c];
    bool pm_r = vmask[r * NPART + p] != 0;
    bool pm_c = vmask[c * NPART + p] != 0;
    bool am_c = tmask[c * NPART + p] != 0;
    bool b1c = g_boost1[p * 256 + c] != 0;
    bool b2r = g_boost2[p * 256 + r] != 0;
    float Lp = softplusf(6.f - 10.f * s);
    float Ln = softplusf(40.f * s - 16.f);
    float v = 0.f;
    if (pm_r && am_c)          v += (match || b1c) ? Lp : Ln;   // b1 term
    if (pm_r && pm_c && am_c)  v += (match || b2r) ? Lp : Ln;   // b2 term (transposed form)
    float tot = blockReduceSum(v, sred);
    if (threadIdx.x == 0) atomicAdd(&g_accum[2], tot);
}

// ---------------- mask loss ----------------
__global__ void k_mask(const float* __restrict__ seg, const int* __restrict__ masks) {
    __shared__ float sred[8];
    int n = blockIdx.x;
    const float* base = seg + (long long)n * NSEGC * NPIX;
    const int* mb = masks + n * NPIX;
    float lsum = 0.f;
    for (int pix = threadIdx.x; pix < NPIX; pix += blockDim.x) {
        float x[NSEGC];
        #pragma unroll
        for (int ch = 0; ch < NSEGC; ch++) x[ch] = base[ch * NPIX + pix];
        float m = x[0];
        #pragma unroll
        for (int ch = 1; ch < NSEGC; ch++) m = fmaxf(m, x[ch]);
        float s = 0.f;
        #pragma unroll
        for (int ch = 0; ch < NSEGC; ch++) s += __expf(x[ch] - m);
        int k = mb[pix];
        lsum += m + __logf(s) - x[k];
    }
    float tot = blockReduceSum(lsum, sred);
    if (threadIdx.x == 0) atomicAdd(&g_accum[0], tot);
}

// ---------------- finalize ----------------
__global__ void k_final(float* __restrict__ out) {
    __shared__ float sred[512];
    int t = threadIdx.x;
    float v = logf(g_rowSumExp[t]) + SCALE_C - g_labelLogit[t];
    sred[t] = v;
    __syncthreads();
    for (int o = 256; o; o >>= 1) {
        if (t < o) sred[t] += sred[t + o];
        __syncthreads();
    }
    if (t == 0) {
        out[0] = sred[0] / 256.f;                                 // instance (v+t)
        out[1] = 5.f * g_accum[0] / (1280.f * 4096.f);            // mask
        out[2] = 2.f * g_accum[1] / 256.f;                        // global align
        out[3] = g_accum[2] / (5.f * 256.f);                      // local align
    }
}

// ---------------- launch ----------------
extern "C" void kernel_launch(void* const* d_in, const int* in_sizes, int n_in,
                              void* d_out, int out_size) {
    const float* vis    = (const float*)d_in[0];
    const float* txt    = (const float*)d_in[1];
    const float* pe     = (const float*)d_in[2];
    const float* ae     = (const float*)d_in[3];
    const float* seg    = (const float*)d_in[4];
    const float* W      = (const float*)d_in[5];
    const int*   labels = (const int*)d_in[6];
    const int*   masks  = (const int*)d_in[7];
    const int*   vmask  = (const int*)d_in[8];
    const int*   tmask  = (const int*)d_in[9];
    float* out = (float*)d_out;

    k_init<<<5, 256>>>();
    k_colnorm<<<(NCLS + 255) / 256, 256>>>(W);
    k_rownorm<<<384, 256>>>(vis, txt, pe, ae);
    k_instance<<<dim3((NCLS + 127) / 128, 4), 256>>>(vis, txt, W, labels);
    k_sim<<<dim3(4, 4, 6), 256>>>(vis, txt, pe, ae, labels);
    k_top8<<<dim3(32, NPART), 256>>>(0);
    k_top8<<<dim3(32, NPART), 256>>>(1);
    k_boost<<<1, 128>>>();
    k_local<<<dim3(256, NPART), 256>>>(labels, vmask, tmask);
    k_mask<<<1280, 256>>>(seg, masks);
    k_final<<<1, 512>>>(out);
}

// round 6
// speedup vs baseline: 1.5314x; 1.5314x over previous
#include <cuda_runtime.h>
#include <cuda_bf16.h>
#include <cstdint>

#define DIMK   512
#define NCLS   11003
#define NCPAD  11008
#define NBATCH 256
#define NPART  5
#define NSEGC  6
#define NPIX   4096
#define SCALE_C 28.0f

// ---------------- device scratch (no allocations allowed) ----------------
__device__ float g_invW[NCPAD];
__device__ float g_invRow[3072];          // [0,512) v|t, [512,1792) part, [1792,3072) attr
__device__ float g_rowSumExp[512];
__device__ float g_labelLogit[512];
__device__ float g_sim[NPART * 256 * 256];
__device__ int   g_rowTop[NPART * 256 * 8];
__device__ int   g_colTop[NPART * 256 * 8];
__device__ unsigned char g_boost1[NPART * 256];
__device__ unsigned char g_boost2[NPART * 256];
__device__ float g_accum[4];              // 0: mask ce, 1: global, 2: local

// bf16 split operands (normalization folded in). W transposed to K-major [NCPAD][512].
__device__ __align__(16) __nv_bfloat16 g_Ahi[512 * DIMK];
__device__ __align__(16) __nv_bfloat16 g_Alo[512 * DIMK];
__device__ __align__(16) __nv_bfloat16 g_Whi[NCPAD * DIMK];
__device__ __align__(16) __nv_bfloat16 g_Wlo[NCPAD * DIMK];

// ---------------- helpers ----------------
__device__ __forceinline__ uint32_t smem_u32(const void* p) {
    uint32_t a;
    asm("{ .reg .u64 t; cvta.to.shared.u64 t, %1; cvt.u32.u64 %0, t; }" : "=r"(a) : "l"(p));
    return a;
}
#define CP16(dst, src) asm volatile("cp.async.cg.shared.global [%0], [%1], 16;" :: "r"(dst), "l"(src))
#define CP_COMMIT()    asm volatile("cp.async.commit_group;" ::: "memory")

__device__ __forceinline__ void ldm4(uint32_t* r, uint32_t addr) {
    asm volatile("ldmatrix.sync.aligned.m8n8.x4.shared.b16 {%0,%1,%2,%3}, [%4];"
                 : "=r"(r[0]), "=r"(r[1]), "=r"(r[2]), "=r"(r[3]) : "r"(addr));
}
__device__ __forceinline__ void mma16816(float* c, const uint32_t* a, uint32_t b0, uint32_t b1) {
    asm volatile("mma.sync.aligned.m16n8k16.row.col.f32.bf16.bf16.f32 "
                 "{%0,%1,%2,%3}, {%4,%5,%6,%7}, {%8,%9}, {%0,%1,%2,%3};"
                 : "+f"(c[0]), "+f"(c[1]), "+f"(c[2]), "+f"(c[3])
                 : "r"(a[0]), "r"(a[1]), "r"(a[2]), "r"(a[3]), "r"(b0), "r"(b1));
}

__device__ __forceinline__ float softplusf(float x) {
    return x > 15.f ? x : log1pf(__expf(x));
}
__device__ __forceinline__ float blockReduceSum(float v, float* sh) {
    int t = threadIdx.x;
    #pragma unroll
    for (int o = 16; o; o >>= 1) v += __shfl_xor_sync(0xffffffffu, v, o);
    if ((t & 31) == 0) sh[t >> 5] = v;
    __syncthreads();
    int nw = (blockDim.x + 31) >> 5;
    if (t < 32) {
        v = (t < nw) ? sh[t] : 0.f;
        #pragma unroll
        for (int o = 16; o; o >>= 1) v += __shfl_xor_sync(0xffffffffu, v, o);
    }
    return v;
}

// ---------------- init ----------------
__global__ void k_init() {
    int t = blockIdx.x * blockDim.x + threadIdx.x;
    if (t < 512) { g_rowSumExp[t] = 0.f; g_labelLogit[t] = 0.f; }
    if (t < NPART * 256) { g_boost1[t] = 0; g_boost2[t] = 0; }
    if (t < 4) g_accum[t] = 0.f;
}

// ---------------- W column inverse norms ----------------
__global__ void k_colnorm(const float* __restrict__ W) {
    int c = blockIdx.x * blockDim.x + threadIdx.x;
    if (c >= NCLS) return;
    float s = 0.f;
    #pragma unroll 8
    for (int d = 0; d < DIMK; d++) {
        float w = W[d * NCLS + c];
        s = fmaf(w, w, s);
    }
    g_invW[c] = rsqrtf(s);
}

// ---------------- row inverse norms (v,t,part,attr) ----------------
__global__ void k_rownorm(const float* __restrict__ vis, const float* __restrict__ txt,
                          const float* __restrict__ pe, const float* __restrict__ ae) {
    int warp = (blockIdx.x * blockDim.x + threadIdx.x) >> 5;
    int lane = threadIdx.x & 31;
    if (warp >= 3072) return;
    const float* src;
    if (warp < 256)       src = vis + warp * DIMK;
    else if (warp < 512)  src = txt + (warp - 256) * DIMK;
    else if (warp < 1792) src = pe + (warp - 512) * DIMK;
    else                  src = ae + (warp - 1792) * DIMK;
    float s = 0.f;
    #pragma unroll 4
    for (int j = lane; j < DIMK; j += 32) { float v = src[j]; s = fmaf(v, v, s); }
    #pragma unroll
    for (int o = 16; o; o >>= 1) s += __shfl_xor_sync(0xffffffffu, s, o);
    if (!lane) g_invRow[warp] = rsqrtf(s);
}

// ---------------- prep A: normalized bf16 hi/lo split of stacked [vis; txt] ----------------
__global__ void k_prepA(const float* __restrict__ vis, const float* __restrict__ txt) {
    int row = blockIdx.x;
    const float* src = (row < 256) ? (vis + row * DIMK) : (txt + (row - 256) * DIMK);
    float inv = g_invRow[row];
    for (int j = threadIdx.x; j < DIMK; j += blockDim.x) {
        float x = src[j] * inv;
        __nv_bfloat16 hi = __float2bfloat16(x);
        __nv_bfloat16 lo = __float2bfloat16(x - __bfloat162float(hi));
        g_Ahi[row * DIMK + j] = hi;
        g_Alo[row * DIMK + j] = lo;
    }
}

// ---------------- prep W: normalize, transpose to [NCPAD][512] K-major, bf16 hi/lo ----------------
__global__ __launch_bounds__(256) void k_prepW(const float* __restrict__ W) {
    __shared__ float sh[32][33];
    int c0 = blockIdx.x * 32;
    int d0 = blockIdx.y * 32;
    int tx = threadIdx.x & 31;
    int ty = threadIdx.x >> 5;     // 0..7
    #pragma unroll
    for (int j = 0; j < 4; j++) {
        int d = d0 + ty + j * 8;
        int c = c0 + tx;
        sh[ty + j * 8][tx] = (c < NCLS) ? W[d * NCLS + c] : 0.f;
    }
    __syncthreads();
    #pragma unroll
    for (int j = 0; j < 4; j++) {
        int c = c0 + ty + j * 8;
        int d = d0 + tx;
        float inv = (c < NCLS) ? g_invW[c] : 0.f;
        float x = sh[tx][ty + j * 8] * inv;
        __nv_bfloat16 hi = __float2bfloat16(x);
        __nv_bfloat16 lo = __float2bfloat16(x - __bfloat162float(hi));
        g_Whi[c * DIMK + d] = hi;
        g_Wlo[c * DIMK + d] = lo;
    }
}

// ---------------- instance loss: mma.sync bf16-split GEMM + online sumexp ----------------
// CTA: M128 x N64, 256 thr (8 warps, 4M x 2N, warp tile 32x32).
// K: 16 chunks of 32, cp.async double-buffered. smem rows are 80B (conflict-free ldmatrix).
#define ROWB     80
#define A_BYTES  (128 * ROWB)             // 10240
#define B_BYTES  (64 * ROWB)              // 5120
#define BUF_BYTES (2 * A_BYTES + 2 * B_BYTES)   // 30720
#define OFF_AHI  0
#define OFF_ALO  A_BYTES
#define OFF_BHI  (2 * A_BYTES)
#define OFF_BLO  (2 * A_BYTES + B_BYTES)
#define SM_TOTAL (2 * BUF_BYTES)          // 61440

__global__ __launch_bounds__(256, 2) void k_mma(const int* __restrict__ labels) {
    extern __shared__ char smem[];
    const int tid = threadIdx.x;
    const int wid = tid >> 5, lane = tid & 31;
    const int row0 = blockIdx.y * 128;
    const int col0 = blockIdx.x * 64;
    const int warpM = wid & 3;            // 0..3 (32 rows each)
    const int warpN = wid >> 2;           // 0..1 (32 cols each)
    const uint32_t sbase = smem_u32(smem);

    float acc[2][4][4];
    #pragma unroll
    for (int i = 0; i < 2; i++)
        #pragma unroll
        for (int j = 0; j < 4; j++)
            #pragma unroll
            for (int k = 0; k < 4; k++) acc[i][j][k] = 0.f;

    // ---- async loader: one k-chunk (32 cols) into buffer `buf` ----
    auto load_chunk = [&](int kc, int buf) {
        uint32_t b = sbase + buf * BUF_BYTES;
        {
            int r = tid >> 1, h = tid & 1;                 // 128 rows x 2 halves
            long off = (long)(row0 + r) * DIMK + kc * 32 + h * 16;
            uint32_t d = b + OFF_AHI + r * ROWB + h * 32;
            CP16(d,      g_Ahi + off);
            CP16(d + 16, g_Ahi + off + 8);
            d = b + OFF_ALO + r * ROWB + h * 32;
            CP16(d,      g_Alo + off);
            CP16(d + 16, g_Alo + off + 8);
        }
        if (tid < 128) {
            int r = tid >> 1, h = tid & 1;                 // 64 rows x 2 halves
            long off = (long)(col0 + r) * DIMK + kc * 32 + h * 16;
            uint32_t d = b + OFF_BHI + r * ROWB + h * 32;
            CP16(d,      g_Whi + off);
            CP16(d + 16, g_Whi + off + 8);
            d = b + OFF_BLO + r * ROWB + h * 32;
            CP16(d,      g_Wlo + off);
            CP16(d + 16, g_Wlo + off + 8);
        }
    };

    load_chunk(0, 0);
    CP_COMMIT();

    for (int kc = 0; kc < 16; kc++) {
        int buf = kc & 1;
        if (kc < 15) {
            load_chunk(kc + 1, buf ^ 1);
            CP_COMMIT();
            asm volatile("cp.async.wait_group 1;" ::: "memory");
        } else {
            asm volatile("cp.async.wait_group 0;" ::: "memory");
        }
        __syncthreads();

        uint32_t b = sbase + buf * BUF_BYTES;
        #pragma unroll
        for (int ks = 0; ks < 2; ks++) {
            uint32_t ah[2][4], al[2][4], bh[2][4], bl[2][4];
            // A: lane l -> row mrow0+mi*16+(l&15), 16B chunk ks*2+(l>>4)
            #pragma unroll
            for (int mi = 0; mi < 2; mi++) {
                uint32_t ra = (uint32_t)((warpM * 32 + mi * 16 + (lane & 15)) * ROWB +
                                         (ks * 2 + (lane >> 4)) * 16);
                ldm4(ah[mi], b + OFF_AHI + ra);
                ldm4(al[mi], b + OFF_ALO + ra);
            }
            // B: load j covers n16: lane l -> row nrow0+j*16+((l>>4)*8)+(l&7), chunk ks*2+((l>>3)&1)
            #pragma unroll
            for (int j = 0; j < 2; j++) {
                uint32_t rb = (uint32_t)((warpN * 32 + j * 16 + ((lane >> 4) << 3) + (lane & 7)) * ROWB +
                                         (ks * 2 + ((lane >> 3) & 1)) * 16);
                ldm4(bh[j], b + OFF_BHI + rb);
                ldm4(bl[j], b + OFF_BLO + rb);
            }
            #pragma unroll
            for (int mi = 0; mi < 2; mi++) {
                #pragma unroll
                for (int ni = 0; ni < 4; ni++) {
                    int j = ni >> 1, loc = ni & 1;
                    mma16816(acc[mi][ni], ah[mi], bh[j][loc * 2], bh[j][loc * 2 + 1]);
                    mma16816(acc[mi][ni], ah[mi], bl[j][loc * 2], bl[j][loc * 2 + 1]);
                    mma16816(acc[mi][ni], al[mi], bh[j][loc * 2], bh[j][loc * 2 + 1]);
                }
            }
        }
        __syncthreads();
    }

    // ---- epilogue: logits -> shifted sumexp + label capture ----
    int q = lane >> 2, qc = lane & 3;
    #pragma unroll
    for (int mi = 0; mi < 2; mi++) {
        #pragma unroll
        for (int half = 0; half < 2; half++) {
            int row = row0 + warpM * 32 + mi * 16 + half * 8 + q;
            int lbl = labels[row & 255];
            float rs = 0.f;
            #pragma unroll
            for (int ni = 0; ni < 4; ni++) {
                #pragma unroll
                for (int j = 0; j < 2; j++) {
                    int c = col0 + warpN * 32 + ni * 8 + qc * 2 + j;
                    if (c < NCLS) {
                        float lg = SCALE_C * acc[mi][ni][half * 2 + j];
                        rs += __expf(lg - SCALE_C);
                        if (c == lbl) g_labelLogit[row] = lg;
                    }
                }
            }
            rs += __shfl_xor_sync(0xffffffffu, rs, 1);
            rs += __shfl_xor_sync(0xffffffffu, rs, 2);
            if (qc == 0) atomicAdd(&g_rowSumExp[row], rs);
        }
    }
}

// ---------------- sim GEMMs: z=0 global align (fused), z=1..5 part sims to scratch ----------------
__global__ __launch_bounds__(256) void k_sim(
    const float* __restrict__ vis, const float* __restrict__ txt,
    const float* __restrict__ pe, const float* __restrict__ ae,
    const int* __restrict__ labels) {
    __shared__ float As[32][68];
    __shared__ float Bs[32][68];
    __shared__ float sred[8];
    int z = blockIdx.z;
    int tid = threadIdx.x;
    int tx = tid & 15, ty = tid >> 4;
    int r0 = blockIdx.y * 64, c0 = blockIdx.x * 64;

    const float* abase; const float* bbase; int aIdx, bIdx;
    if (z == 0) { abase = vis; bbase = txt; aIdx = 0; bIdx = 256; }
    else {
        int p = z - 1;
        abase = pe + p * 256 * DIMK; bbase = ae + p * 256 * DIMK;
        aIdx = 512 + p * 256; bIdx = 1792 + p * 256;
    }

    float acc[4][4];
    #pragma unroll
    for (int i = 0; i < 4; i++)
        #pragma unroll
        for (int j = 0; j < 4; j++) acc[i][j] = 0.f;

    int lm = tid >> 2, lseg = tid & 3;
    for (int kt = 0; kt < DIMK; kt += 32) {
        float4 v0 = *(const float4*)(abase + (r0 + lm) * DIMK + kt + lseg * 8);
        float4 v1 = *(const float4*)(abase + (r0 + lm) * DIMK + kt + lseg * 8 + 4);
        As[lseg * 8 + 0][lm] = v0.x; As[lseg * 8 + 1][lm] = v0.y;
        As[lseg * 8 + 2][lm] = v0.z; As[lseg * 8 + 3][lm] = v0.w;
        As[lseg * 8 + 4][lm] = v1.x; As[lseg * 8 + 5][lm] = v1.y;
        As[lseg * 8 + 6][lm] = v1.z; As[lseg * 8 + 7][lm] = v1.w;
        float4 w0 = *(const float4*)(bbase + (c0 + lm) * DIMK + kt + lseg * 8);
        float4 w1 = *(const float4*)(bbase + (c0 + lm) * DIMK + kt + lseg * 8 + 4);
        Bs[lseg * 8 + 0][lm] = w0.x; Bs[lseg * 8 + 1][lm] = w0.y;
        Bs[lseg * 8 + 2][lm] = w0.z; Bs[lseg * 8 + 3][lm] = w0.w;
        Bs[lseg * 8 + 4][lm] = w1.x; Bs[lseg * 8 + 5][lm] = w1.y;
        Bs[lseg * 8 + 6][lm] = w1.z; Bs[lseg * 8 + 7][lm] = w1.w;
        __syncthreads();
        #pragma unroll
        for (int k = 0; k < 32; k++) {
            float4 a = *(const float4*)&As[k][ty * 4];
            float4 bq = *(const float4*)&Bs[k][tx * 4];
            acc[0][0] = fmaf(a.x, bq.x, acc[0][0]); acc[0][1] = fmaf(a.x, bq.y, acc[0][1]);
            acc[0][2] = fmaf(a.x, bq.z, acc[0][2]); acc[0][3] = fmaf(a.x, bq.w, acc[0][3]);
            acc[1][0] = fmaf(a.y, bq.x, acc[1][0]); acc[1][1] = fmaf(a.y, bq.y, acc[1][1]);
            acc[1][2] = fmaf(a.y, bq.z, acc[1][2]); acc[1][3] = fmaf(a.y, bq.w, acc[1][3]);
            acc[2][0] = fmaf(a.z, bq.x, acc[2][0]); acc[2][1] = fmaf(a.z, bq.y, acc[2][1]);
            acc[2][2] = fmaf(a.z, bq.z, acc[2][2]); acc[2][3] = fmaf(a.z, bq.w, acc[2][3]);
            acc[3][0] = fmaf(a.w, bq.x, acc[3][0]); acc[3][1] = fmaf(a.w, bq.y, acc[3][1]);
            acc[3][2] = fmaf(a.w, bq.z, acc[3][2]); acc[3][3] = fmaf(a.w, bq.w, acc[3][3]);
        }
        __syncthreads();
    }

    if (z == 0) {
        float lsum = 0.f;
        #pragma unroll
        for (int ri = 0; ri < 4; ri++) {
            int r = r0 + ty * 4 + ri;
            int lr = labels[r];
            float ia = g_invRow[aIdx + r];
            #pragma unroll
            for (int ci = 0; ci < 4; ci++) {
                int c = c0 + tx * 4 + ci;
                float s = acc[ri][ci] * ia * g_invRow[bIdx + c];
                lsum += (lr == labels[c]) ? softplusf(6.f - 10.f * s)
                                          : softplusf(40.f * s - 16.f);
            }
        }
        float tot = blockReduceSum(lsum, sred);
        if (threadIdx.x == 0) atomicAdd(&g_accum[1], tot);
    } else {
        int p = z - 1;
        #pragma unroll
        for (int ri = 0; ri < 4; ri++) {
            int r = r0 + ty * 4 + ri;
            float ia = g_invRow[aIdx + r];
            #pragma unroll
            for (int ci = 0; ci < 4; ci++) {
                int c = c0 + tx * 4 + ci;
                g_sim[p * 65536 + r * 256 + c] = acc[ri][ci] * ia * g_invRow[bIdx + c];
            }
        }
    }
}

// ---------------- top-8 per row (mode 0) / per column (mode 1) ----------------
__global__ void k_top8(int mode) {
    int p = blockIdx.y;
    int w = threadIdx.x >> 5, lane = threadIdx.x & 31;
    int r = blockIdx.x * 8 + w;
    const float* base = g_sim + p * 65536;
    float v[8];
    #pragma unroll
    for (int j = 0; j < 8; j++) {
        int e = lane + j * 32;
        v[j] = mode ? base[e * 256 + r] : base[r * 256 + e];
    }
    int* out = (mode ? g_colTop : g_rowTop) + (p * 256 + r) * 8;
    for (int it = 0; it < 8; it++) {
        float bv = v[0]; int bj = 0;
        #pragma unroll
        for (int j = 1; j < 8; j++) if (v[j] > bv) { bv = v[j]; bj = j; }
        float mv = bv; int me = lane + bj * 32;
        #pragma unroll
        for (int o = 16; o; o >>= 1) {
            float ov = __shfl_xor_sync(0xffffffffu, mv, o);
            int oe = __shfl_xor_sync(0xffffffffu, me, o);
            if (ov > mv || (ov == mv && oe < me)) { mv = ov; me = oe; }
        }
        if (lane == 0) out[it] = me;
        if ((me & 31) == lane) v[me >> 5] = -__int_as_float(0x7f800000);
    }
}

// ---------------- boosts (mutual top-k check) ----------------
__global__ void k_boost() {
    int t = threadIdx.x;
    if (t >= 80) return;
    int p = t / 16, rem = t % 16, which = rem >> 3, k = rem & 7;
    if (which == 0) {
        int c = g_rowTop[(p * 256 + p) * 8 + k];
        bool hit = false;
        #pragma unroll
        for (int m = 0; m < 8; m++) hit |= (g_colTop[(p * 256 + c) * 8 + m] == p);
        g_boost1[p * 256 + c] = hit ? 1 : 0;
    } else {
        int r = g_colTop[(p * 256 + p) * 8 + k];
        bool hit = false;
        #pragma unroll
        for (int m = 0; m < 8; m++) hit |= (g_rowTop[(p * 256 + r) * 8 + m] == p);
        g_boost2[p * 256 + r] = hit ? 1 : 0;
    }
}

// ---------------- local align weighted sum (masks arrive as int32) ----------------
__global__ void k_local(const int* __restrict__ labels,
                        const int* __restrict__ vmask,
                        const int* __restrict__ tmask) {
    __shared__ float sred[8];
    int p = blockIdx.y;
    int r = blockIdx.x;
    int c = threadIdx.x;
    float s = g_sim[p * 65536 + r * 256 + c];
    bool match = labels[r] == labels[c];
    bool pm_r = vmask[r * NPART + p] != 0;
    bool pm_c = vmask[c * NPART + p] != 0;
    bool am_c = tmask[c * NPART + p] != 0;
    bool b1c = g_boost1[p * 256 + c] != 0;
    bool b2r = g_boost2[p * 256 + r] != 0;
    float Lp = softplusf(6.f - 10.f * s);
    float Ln = softplusf(40.f * s - 16.f);
    float v = 0.f;
    if (pm_r && am_c)          v += (match || b1c) ? Lp : Ln;   // b1 term
    if (pm_r && pm_c && am_c)  v += (match || b2r) ? Lp : Ln;   // b2 term (transposed form)
    float tot = blockReduceSum(v, sred);
    if (threadIdx.x == 0) atomicAdd(&g_accum[2], tot);
}

// ---------------- mask loss ----------------
__global__ void k_mask(const float* __restrict__ seg, const int* __restrict__ masks) {
    __shared__ float sred[8];
    int n = blockIdx.x;
    const float* base = seg + (long long)n * NSEGC * NPIX;
    const int* mb = masks + n * NPIX;
    float lsum = 0.f;
    for (int pix = threadIdx.x; pix < NPIX; pix += blockDim.x) {
        float x[NSEGC];
        #pragma unroll
        for (int ch = 0; ch < NSEGC; ch++) x[ch] = base[ch * NPIX + pix];
        float m = x[0];
        #pragma unroll
        for (int ch = 1; ch < NSEGC; ch++) m = fmaxf(m, x[ch]);
        float s = 0.f;
        #pragma unroll
        for (int ch = 0; ch < NSEGC; ch++) s += __expf(x[ch] - m);
        int k = mb[pix];
        lsum += m + __logf(s) - x[k];
    }
    float tot = blockReduceSum(lsum, sred);
    if (threadIdx.x == 0) atomicAdd(&g_accum[0], tot);
}

// ---------------- finalize ----------------
__global__ void k_final(float* __restrict__ out) {
    __shared__ float sred[512];
    int t = threadIdx.x;
    float v = logf(g_rowSumExp[t]) + SCALE_C - g_labelLogit[t];
    sred[t] = v;
    __syncthreads();
    for (int o = 256; o; o >>= 1) {
        if (t < o) sred[t] += sred[t + o];
        __syncthreads();
    }
    if (t == 0) {
        out[0] = sred[0] / 256.f;                                 // instance (v+t)
        out[1] = 5.f * g_accum[0] / (1280.f * 4096.f);            // mask
        out[2] = 2.f * g_accum[1] / 256.f;                        // global align
        out[3] = g_accum[2] / (5.f * 256.f);                      // local align
    }
}

// ---------------- launch ----------------
extern "C" void kernel_launch(void* const* d_in, const int* in_sizes, int n_in,
                              void* d_out, int out_size) {
    const float* vis    = (const float*)d_in[0];
    const float* txt    = (const float*)d_in[1];
    const float* pe     = (const float*)d_in[2];
    const float* ae     = (const float*)d_in[3];
    const float* seg    = (const float*)d_in[4];
    const float* W      = (const float*)d_in[5];
    const int*   labels = (const int*)d_in[6];
    const int*   masks  = (const int*)d_in[7];
    const int*   vmask  = (const int*)d_in[8];
    const int*   tmask  = (const int*)d_in[9];
    float* out = (float*)d_out;

    static bool attr_done = false;
    if (!attr_done) {
        cudaFuncSetAttribute(k_mma, cudaFuncAttributeMaxDynamicSharedMemorySize, SM_TOTAL);
        attr_done = true;
    }

    k_init<<<5, 256>>>();
    k_colnorm<<<(NCLS + 255) / 256, 256>>>(W);
    k_rownorm<<<384, 256>>>(vis, txt, pe, ae);
    k_prepA<<<512, 256>>>(vis, txt);
    k_prepW<<<dim3(NCPAD / 32, DIMK / 32), 256>>>(W);
    k_mma<<<dim3(NCPAD / 64, 4), 256, SM_TOTAL>>>(labels);
    k_sim<<<dim3(4, 4, 6), 256>>>(vis, txt, pe, ae, labels);
    k_top8<<<dim3(32, NPART), 256>>>(0);
    k_top8<<<dim3(32, NPART), 256>>>(1);
    k_boost<<<1, 128>>>();
    k_local<<<dim3(256, NPART), 256>>>(labels, vmask, tmask);
    k_mask<<<1280, 256>>>(seg, masks);
    k_final<<<1, 512>>>(out);
}